// round 10
// baseline (speedup 1.0000x reference)
#include <cuda_runtime.h>
#include <cuda_fp16.h>
#include <cstdint>

// SpikingMLP:
//   GEMM1 (fp16 m16n8k16 3-pass, w_up*2^8): rate = spike_rate(x @ w_up^T)   [unchanged]
//   GEMM2 (fp16 single pass, w_down*2^4, tile 128x256): out = rate @ w_down^T / 2^4
//   rate_per_unit via exact atomic column sums (zeroed in pack_a, written in GEMM2).

namespace cfg {
constexpr int M  = 4096;
constexpr int Dd = 1024;
constexpr int Ff = 4096;
}

__device__ uint4 g_axh[(size_t)32 * 32 * 512];
__device__ uint4 g_axl[(size_t)32 * 32 * 512];
__device__ uint4 g_buh[(size_t)32 * 32 * 512];
__device__ uint4 g_bul[(size_t)32 * 32 * 512];
__device__ uint4 g_dw[(size_t)cfg::Dd * cfg::Ff / 8];    // w_down * 2^4
__device__ uint4 g_ratep[(size_t)cfg::M * cfg::Ff / 8];  // rate fp16, GEMM2-A packed
__device__ float g_colsum[cfg::Ff];

// ------------------------------------------------------------------ helpers
__device__ __forceinline__ uint32_t pack_h2(float a, float b) {
    __half2 p = __floats2half2_rn(a, b);
    return *(uint32_t*)&p;
}
__device__ __forceinline__ void mma_f16(float c[4], const uint4& a, const uint2& b) {
    asm volatile(
        "mma.sync.aligned.m16n8k16.row.col.f32.f16.f16.f32 "
        "{%0,%1,%2,%3}, {%4,%5,%6,%7}, {%8,%9}, {%0,%1,%2,%3};"
        : "+f"(c[0]), "+f"(c[1]), "+f"(c[2]), "+f"(c[3])
        : "r"(a.x), "r"(a.y), "r"(a.z), "r"(a.w), "r"(b.x), "r"(b.y));
}
__device__ __forceinline__ void cp16(uint32_t sdst, const void* gsrc) {
    asm volatile("cp.async.cg.shared.global [%0], [%1], 16;" :: "r"(sdst), "l"(gsrc));
}
#define CP_COMMIT() asm volatile("cp.async.commit_group;" ::: "memory")

__device__ __forceinline__ float spike_rate_of(float h, float be, int T, float invT) {
    float v = 0.0f; int cnt = 0;
    for (int t = 0; t < T; t++) {
        v = be * v + h;
        if (v > 1.0f) { cnt++; v -= 1.0f; }
    }
    return (float)cnt * invT;
}

// -------------------------------------------------------------- pack kernels
__global__ void pack_a_f16(const float* __restrict__ src,
                           uint4* __restrict__ hi, uint4* __restrict__ lo)
{
    if (blockIdx.x < 16) g_colsum[blockIdx.x * 256 + threadIdx.x] = 0.0f;  // fused zero
    constexpr int K = 1024, KB = K / 16;
    const int wg   = (blockIdx.x * 256 + threadIdx.x) >> 5;
    const int lane = threadIdx.x & 31;
    const int rbg = wg / KB, kbg = wg % KB;
    const int gq = lane >> 2, tq = lane & 3;
    const float* s = src + (size_t)(rbg * 16) * K + kbg * 16;
    float v[8];
    v[0] = s[(size_t)gq * K + 2 * tq];       v[1] = s[(size_t)gq * K + 2 * tq + 1];
    v[2] = s[(size_t)(gq + 8) * K + 2 * tq]; v[3] = s[(size_t)(gq + 8) * K + 2 * tq + 1];
    v[4] = s[(size_t)gq * K + 2 * tq + 8];   v[5] = s[(size_t)gq * K + 2 * tq + 9];
    v[6] = s[(size_t)(gq + 8) * K + 2 * tq + 8]; v[7] = s[(size_t)(gq + 8) * K + 2 * tq + 9];
    float h[8], l[8];
    #pragma unroll
    for (int i = 0; i < 8; i++) {
        h[i] = __half2float(__float2half_rn(v[i]));
        l[i] = v[i] - h[i];
    }
    const int mtile = rbg >> 3, rb = rbg & 7, kc = kbg >> 1, kb = kbg & 1;
    const size_t idx = (((size_t)kc * 32 + mtile) * 16 + rb * 2 + kb) * 32 + lane;
    hi[idx] = make_uint4(pack_h2(h[0], h[1]), pack_h2(h[2], h[3]),
                         pack_h2(h[4], h[5]), pack_h2(h[6], h[7]));
    lo[idx] = make_uint4(pack_h2(l[0], l[1]), pack_h2(l[2], l[3]),
                         pack_h2(l[4], l[5]), pack_h2(l[6], l[7]));
}

__global__ void pack_b_f16(const float* __restrict__ src,
                           uint2* __restrict__ hi, uint2* __restrict__ lo)
{
    constexpr int K = 1024, KB = K / 16;
    const int wg   = (blockIdx.x * 256 + threadIdx.x) >> 5;
    const int lane = threadIdx.x & 31;
    const int nbg = wg / KB, kbg = wg % KB;
    const int gq = lane >> 2, tq = lane & 3;
    const float* s = src + (size_t)(nbg * 8 + gq) * K + kbg * 16;
    const float v0 = s[2 * tq] * 256.0f,     v1 = s[2 * tq + 1] * 256.0f;
    const float v2 = s[2 * tq + 8] * 256.0f, v3 = s[2 * tq + 9] * 256.0f;
    const float h0 = __half2float(__float2half_rn(v0));
    const float h1 = __half2float(__float2half_rn(v1));
    const float h2 = __half2float(__float2half_rn(v2));
    const float h3 = __half2float(__float2half_rn(v3));
    const int ntile = nbg >> 4, nb = nbg & 15, kc = kbg >> 1, kb = kbg & 1;
    const size_t idx = ((((size_t)kc * 32 + ntile) * 16 + nb) * 2 + kb) * 32 + lane;
    hi[idx] = make_uint2(pack_h2(h0, h1), pack_h2(h2, h3));
    lo[idx] = make_uint2(pack_h2(v0 - h0, v1 - h1), pack_h2(v2 - h2, v3 - h3));
}

// w_down [N=1024, K=4096] * 2^4 -> fp16 [kc(64)][ntile(8)][nb(16)][kb(4)][lane] uint2
__global__ void pack_w_down_f16(const float* __restrict__ src,
                                uint2* __restrict__ dst)
{
    constexpr int K = 4096, KB16 = K / 16;
    const int wg   = (blockIdx.x * 256 + threadIdx.x) >> 5;
    const int lane = threadIdx.x & 31;
    const int nbg = wg / KB16, kbg = wg % KB16;
    const int gq = lane >> 2, tq = lane & 3;
    const float* s = src + (size_t)(nbg * 8 + gq) * K + kbg * 16;
    const float v0 = s[2 * tq] * 16.0f,     v1 = s[2 * tq + 1] * 16.0f;
    const float v2 = s[2 * tq + 8] * 16.0f, v3 = s[2 * tq + 9] * 16.0f;
    const int ntile = nbg >> 4, nb = nbg & 15, kc = kbg >> 2, kb = kbg & 3;
    const size_t idx = ((((size_t)kc * 8 + ntile) * 16 + nb) * 4 + kb) * 32 + lane;
    dst[idx] = make_uint2(pack_h2(v0, v1), pack_h2(v2, v3));
}

// --------------------------------------------------- GEMM1 (fp16, 3 passes)  [unchanged]
__global__ __launch_bounds__(256, 2)
void tc_gemm1(const float* __restrict__ beta, const int* __restrict__ Tptr)
{
    constexpr int TILE  = 8192;
    constexpr int STAGE = 4 * TILE;
    constexpr int NC    = cfg::Dd / 32;
    constexpr int STAGES = 3;
    extern __shared__ char smc[];

    const int tid = threadIdx.x, lane = tid & 31, wid = tid >> 5;
    const int gq = lane >> 2, tq = lane & 3;
    const int mtile = blockIdx.y, ntile = blockIdx.x;
    const int colBase = ntile * 128;
    const int rbb = (wid & 1) * 4, nbb = (wid >> 1) * 4;
    const int wm = (wid & 1) * 64, wn = (wid >> 1) * 32;
    const uint32_t sb = (uint32_t)__cvta_generic_to_shared(smc);
    float* sm = (float*)smc;

    const uint4* pAh = g_axh + (size_t)mtile * 512;
    const uint4* pAl = g_axl + (size_t)mtile * 512;
    const uint4* pBh = g_buh + (size_t)ntile * 512;
    const uint4* pBl = g_bul + (size_t)ntile * 512;
    constexpr size_t strideKC = (size_t)32 * 512;

    auto stage_load = [&](int c, int st) {
        const uint32_t d = sb + (uint32_t)st * STAGE;
        const size_t o = (size_t)c * strideKC;
        #pragma unroll
        for (int q = 0; q < 2; q++) {
            const int idx = q * 256 + tid;
            cp16(d + idx * 16,            pAh + o + idx);
            cp16(d + TILE + idx * 16,     pAl + o + idx);
            cp16(d + 2 * TILE + idx * 16, pBh + o + idx);
            cp16(d + 3 * TILE + idx * 16, pBl + o + idx);
        }
    };

    float acc[4][4][4];
    #pragma unroll
    for (int mi = 0; mi < 4; mi++)
        #pragma unroll
        for (int ni = 0; ni < 4; ni++)
            #pragma unroll
            for (int q = 0; q < 4; q++) acc[mi][ni][q] = 0.0f;

    #pragma unroll
    for (int s = 0; s < STAGES; s++) { stage_load(s, s); CP_COMMIT(); }

    int st = 0;
    for (int c = 0; c < NC; c++) {
        asm volatile("cp.async.wait_group 2;" ::: "memory");
        __syncthreads();
        const uint4* ahs = (const uint4*)(smc + st * STAGE);
        const uint4* als = (const uint4*)(smc + st * STAGE + TILE);
        const uint2* bhs = (const uint2*)(smc + st * STAGE + 2 * TILE);
        const uint2* bls = (const uint2*)(smc + st * STAGE + 3 * TILE);

        #pragma unroll
        for (int ks = 0; ks < 2; ks++) {
            uint2 bh[4], bl[4];
            #pragma unroll
            for (int ni = 0; ni < 4; ni++) {
                bh[ni] = bhs[((nbb + ni) * 2 + ks) * 32 + lane];
                bl[ni] = bls[((nbb + ni) * 2 + ks) * 32 + lane];
            }
            #pragma unroll
            for (int mp = 0; mp < 2; mp++) {
                const int m0 = 2 * mp, m1 = 2 * mp + 1;
                const uint4 a0 = ahs[((rbb + m0) * 2 + ks) * 32 + lane];
                const uint4 a1 = ahs[((rbb + m1) * 2 + ks) * 32 + lane];
                #pragma unroll
                for (int ni = 0; ni < 4; ni++) mma_f16(acc[m0][ni], a0, bh[ni]);
                #pragma unroll
                for (int ni = 0; ni < 4; ni++) mma_f16(acc[m1][ni], a1, bh[ni]);
                #pragma unroll
                for (int ni = 0; ni < 4; ni++) mma_f16(acc[m0][ni], a0, bl[ni]);
                #pragma unroll
                for (int ni = 0; ni < 4; ni++) mma_f16(acc[m1][ni], a1, bl[ni]);
                const uint4 l0 = als[((rbb + m0) * 2 + ks) * 32 + lane];
                const uint4 l1 = als[((rbb + m1) * 2 + ks) * 32 + lane];
                #pragma unroll
                for (int ni = 0; ni < 4; ni++) mma_f16(acc[m0][ni], l0, bh[ni]);
                #pragma unroll
                for (int ni = 0; ni < 4; ni++) mma_f16(acc[m1][ni], l1, bh[ni]);
            }
        }
        __syncthreads();
        if (c + STAGES < NC) stage_load(c + STAGES, st);
        CP_COMMIT();
        st = (st + 1 == STAGES) ? 0 : st + 1;
    }

    constexpr float SC = 1.0f / 256.0f;
    const int   T    = *Tptr;
    const float invT = 1.0f / (float)T;
    __syncthreads();
    #pragma unroll
    for (int ni = 0; ni < 4; ni++) {
        const int cl = wn + ni * 8 + 2 * tq;
        const float be0 = beta[colBase + cl];
        const float be1 = beta[colBase + cl + 1];
        #pragma unroll
        for (int mi = 0; mi < 4; mi++) {
            const int r0 = wm + mi * 16 + gq;
            sm[r0 * 132 + cl]           = spike_rate_of(acc[mi][ni][0] * SC, be0, T, invT);
            sm[r0 * 132 + cl + 1]       = spike_rate_of(acc[mi][ni][1] * SC, be1, T, invT);
            sm[(r0 + 8) * 132 + cl]     = spike_rate_of(acc[mi][ni][2] * SC, be0, T, invT);
            sm[(r0 + 8) * 132 + cl + 1] = spike_rate_of(acc[mi][ni][3] * SC, be1, T, invT);
        }
    }
    __syncthreads();
    if (tid < 128) {
        float s = 0.0f;
        #pragma unroll 8
        for (int r = 0; r < 128; r++) s += sm[r * 132 + tid];
        atomicAdd(&g_colsum[colBase + tid], s);   // exact: multiples of 1/8
    }
    #pragma unroll
    for (int i = 0; i < 8; i++) {
        const int idx = i * 256 + tid;
        const int l2  = idx & 31;
        const int t2  = idx >> 5;
        const int kcj = t2 >> 5;
        const int pos = t2 & 31;
        const int g2 = l2 >> 2, q2 = l2 & 3;
        const int ml = (pos >> 2) * 16;
        const int fl = kcj * 64 + (pos & 3) * 16;
        const int ra = ml + g2, rb2 = ml + g2 + 8;
        const int c0 = fl + 2 * q2, c8 = fl + 2 * q2 + 8;
        uint4 v;
        v.x = pack_h2(sm[ra * 132 + c0],  sm[ra * 132 + c0 + 1]);
        v.y = pack_h2(sm[rb2 * 132 + c0], sm[rb2 * 132 + c0 + 1]);
        v.z = pack_h2(sm[ra * 132 + c8],  sm[ra * 132 + c8 + 1]);
        v.w = pack_h2(sm[rb2 * 132 + c8], sm[rb2 * 132 + c8 + 1]);
        g_ratep[((size_t)(colBase / 64 + kcj) * 32 + mtile) * 1024 + pos * 32 + l2] = v;
    }
}

// --------------------------------------------- GEMM2 (fp16, tile 128x256, 512 thr)
// out[M, Dd] = (rate @ (w_down*16)^T) * 2^-4.  Also writes rate_per_unit (CTA 0,0).
__global__ __launch_bounds__(512, 1)
void tc_gemm2(const uint4* __restrict__ A, const uint4* __restrict__ B,
              float* __restrict__ C, float* __restrict__ rpu)
{
    constexpr int ATILE = 16384;                 // 128x64 fp16
    constexpr int BTILE = 32768;                 // 256x64 fp16
    constexpr int STAGE = ATILE + BTILE;
    constexpr int NC = cfg::Ff / 64;             // 64
    constexpr int STAGES = 3;                    // 144 KB
    extern __shared__ char smc[];

    const int tid = threadIdx.x, lane = tid & 31, wid = tid >> 5;
    const int gq = lane >> 2, tq = lane & 3;
    const int mtile = blockIdx.y;                // 0..31
    const int npair = blockIdx.x;                // 0..3 (pairs of 128-col ntiles)
    const int rowBase = mtile * 128, colBase = npair * 256;
    const int wm = wid & 3, wn = wid >> 2;       // 4(M) x 4(N) warps, tile 32x64
    const uint32_t sb = (uint32_t)__cvta_generic_to_shared(smc);

    // fused rate_per_unit (colsum final after GEMM1)
    if (mtile == 0 && npair == 0) {
        #pragma unroll
        for (int i = 0; i < 8; i++)
            rpu[i * 512 + tid] = g_colsum[i * 512 + tid] * (1.0f / (float)cfg::M);
    }

    const uint4* pA = A + (size_t)mtile * 1024;
    const uint4* pB = B + (size_t)(npair * 2) * 1024;
    constexpr size_t strideA = (size_t)32 * 1024;   // per kc (uint4)
    constexpr size_t strideB = (size_t)8 * 1024;

    auto stage_load = [&](int c, int st) {
        const uint32_t d = sb + (uint32_t)st * STAGE;
        const uint4* a = pA + (size_t)c * strideA;
        const uint4* b = pB + (size_t)c * strideB;
        #pragma unroll
        for (int q = 0; q < 2; q++) { const int i = q * 512 + tid; cp16(d + i * 16, a + i); }
        #pragma unroll
        for (int q = 0; q < 4; q++) { const int i = q * 512 + tid; cp16(d + ATILE + i * 16, b + i); }
    };

    float acc[2][8][4];
    #pragma unroll
    for (int mi = 0; mi < 2; mi++)
        #pragma unroll
        for (int ni = 0; ni < 8; ni++)
            #pragma unroll
            for (int q = 0; q < 4; q++) acc[mi][ni][q] = 0.0f;

    #pragma unroll
    for (int s = 0; s < STAGES; s++) { stage_load(s, s); CP_COMMIT(); }

    int st = 0;
    for (int c = 0; c < NC; c++) {
        asm volatile("cp.async.wait_group 2;" ::: "memory");
        __syncthreads();
        const uint4* ahs = (const uint4*)(smc + st * STAGE);
        const uint2* bhs = (const uint2*)(smc + st * STAGE + ATILE);

        #pragma unroll
        for (int ks = 0; ks < 4; ks++) {
            uint2 bfr[8];
            #pragma unroll
            for (int ni = 0; ni < 8; ni++)
                bfr[ni] = bhs[((wn * 8 + ni) * 4 + ks) * 32 + lane];
            #pragma unroll
            for (int mi = 0; mi < 2; mi++) {
                const uint4 a = ahs[((wm * 2 + mi) * 4 + ks) * 32 + lane];
                #pragma unroll
                for (int ni = 0; ni < 8; ni++) mma_f16(acc[mi][ni], a, bfr[ni]);
            }
        }
        __syncthreads();
        if (c + STAGES < NC) stage_load(c + STAGES, st);
        CP_COMMIT();
        st = (st + 1 == STAGES) ? 0 : st + 1;
    }

    constexpr float SC = 1.0f / 16.0f;
    #pragma unroll
    for (int ni = 0; ni < 8; ni++) {
        const int cglob = colBase + wn * 64 + ni * 8 + 2 * tq;
        #pragma unroll
        for (int mi = 0; mi < 2; mi++) {
            const int r0 = rowBase + wm * 32 + mi * 16 + gq;
            *(float2*)(C + (size_t)r0 * cfg::Dd + cglob) =
                make_float2(acc[mi][ni][0] * SC, acc[mi][ni][1] * SC);
            *(float2*)(C + (size_t)(r0 + 8) * cfg::Dd + cglob) =
                make_float2(acc[mi][ni][2] * SC, acc[mi][ni][3] * SC);
        }
    }
}

// -------------------------------------------------------------------- launch
extern "C" void kernel_launch(void* const* d_in, const int* in_sizes, int n_in,
                              void* d_out, int out_size)
{
    const float* x      = (const float*)d_in[0];
    const float* w_up   = (const float*)d_in[1];
    const float* w_down = (const float*)d_in[2];
    const float* beta   = (const float*)d_in[3];
    const int*   Tptr   = (const int*)d_in[4];

    float* out = (float*)d_out;
    float* rpu = out + (size_t)cfg::M * cfg::Dd;

    uint4 *axh, *axl, *buh, *bul, *dw, *ratep;
    cudaGetSymbolAddress((void**)&axh, g_axh);
    cudaGetSymbolAddress((void**)&axl, g_axl);
    cudaGetSymbolAddress((void**)&buh, g_buh);
    cudaGetSymbolAddress((void**)&bul, g_bul);
    cudaGetSymbolAddress((void**)&dw, g_dw);
    cudaGetSymbolAddress((void**)&ratep, g_ratep);

    pack_a_f16<<<2048, 256>>>(x, axh, axl);                      // + colsum zero
    pack_b_f16<<<4096, 256>>>(w_up, (uint2*)buh, (uint2*)bul);
    pack_w_down_f16<<<4096, 256>>>(w_down, (uint2*)dw);

    constexpr int SMEM1 = 3 * 4 * 8192;            // 98304 B
    constexpr int SMEM2 = 3 * (16384 + 32768);     // 147456 B
    cudaFuncSetAttribute(tc_gemm1, cudaFuncAttributeMaxDynamicSharedMemorySize, SMEM1);
    cudaFuncSetAttribute(tc_gemm2, cudaFuncAttributeMaxDynamicSharedMemorySize, SMEM2);

    tc_gemm1<<<dim3(cfg::Ff / 128, cfg::M / 128), 256, SMEM1>>>(beta, Tptr);

    tc_gemm2<<<dim3(cfg::Dd / 256, cfg::M / 128), 512, SMEM2>>>(ratep, dw, out, rpu);
}